// round 2
// baseline (speedup 1.0000x reference)
#include <cuda_runtime.h>
#include <math.h>

// Problem constants
// colors [4,16384,64,32] f32, densities [4,16384,64,1], depths [4,16384,64,1], grads [4,16384,64,3]
// outputs concatenated: rgb [65536,32], depth [65536,1], weights [65536,63], grad [65536,3]
#define FULL 0xFFFFFFFFu

static constexpr int  RAYS       = 65536;
static constexpr long long OFF_DEPTH = 2097152;          // 65536*32
static constexpr long long OFF_W     = 2162688;          // + 65536
static constexpr long long OFF_G     = 6291456;          // + 65536*63
static constexpr int  N_DEPTH_ELEMS  = 4 * 16384 * 64;   // 4194304

__device__ unsigned g_min_bits;
__device__ unsigned g_max_bits;

__device__ __forceinline__ unsigned flipf(float f) {
    unsigned u = __float_as_uint(f);
    return u ^ ((unsigned)((int)u >> 31) | 0x80000000u);
}
__device__ __forceinline__ float unflipf(unsigned u) {
    unsigned m = (u & 0x80000000u) ? 0x80000000u : 0xFFFFFFFFu;
    return __uint_as_float(u ^ m);
}

__global__ void mm_init_kernel() {
    g_min_bits = 0xFFFFFFFFu;
    g_max_bits = 0u;
}

__global__ void mm_reduce_kernel(const float4* __restrict__ p, int n4) {
    unsigned mn = 0xFFFFFFFFu, mx = 0u;
    for (int i = blockIdx.x * blockDim.x + threadIdx.x; i < n4;
         i += gridDim.x * blockDim.x) {
        float4 v = p[i];
        unsigned a = flipf(v.x), b = flipf(v.y), c = flipf(v.z), d = flipf(v.w);
        mn = min(mn, min(min(a, b), min(c, d)));
        mx = max(mx, max(max(a, b), max(c, d)));
    }
    mn = __reduce_min_sync(FULL, mn);
    mx = __reduce_max_sync(FULL, mx);
    if ((threadIdx.x & 31) == 0) {
        atomicMin(&g_min_bits, mn);
        atomicMax(&g_max_bits, mx);
    }
}

__device__ __forceinline__ float softplus_f(float x) {
    // jax.nn.softplus(x) = max(x,0) + log1p(exp(-|x|))
    return fmaxf(x, 0.0f) + log1pf(__expf(-fabsf(x)));
}

__global__ __launch_bounds__(256) void march_kernel(
    const float* __restrict__ colors,
    const float* __restrict__ dens,
    const float* __restrict__ dep,
    const float* __restrict__ grads,
    float* __restrict__ out)
{
    __shared__ float s_v[8][64];

    const int lane = threadIdx.x & 31;
    const int w    = threadIdx.x >> 5;
    const int ray  = blockIdx.x * 8 + w;

    // ---- per-ray scalar streams: depths & densities (64 each) ----
    const float* zb = dep  + (long long)ray * 64;
    const float* db = dens + (long long)ray * 64;
    float z0 = zb[lane], z1 = zb[lane + 32];
    float d0 = db[lane], d1 = db[lane + 32];

    // neighbor values (sample s+1)
    float z0n = __shfl_down_sync(FULL, z0, 1);
    float d0n = __shfl_down_sync(FULL, d0, 1);
    float zcross = __shfl_sync(FULL, z1, 0);
    float dcross = __shfl_sync(FULL, d1, 0);
    if (lane == 31) { z0n = zcross; d0n = dcross; }
    float z1n = __shfl_down_sync(FULL, z1, 1);   // lane31 unused
    float d1n = __shfl_down_sync(FULL, d1, 1);

    // ---- alphas (interval s = lane and s = 32+lane) ----
    float delta0 = z0n - z0;
    float dm0    = 0.5f * (d0 + d0n) - 1.0f;
    float a0     = 1.0f - __expf(-softplus_f(dm0) * delta0);

    float a1 = 0.0f;
    if (lane < 31) {
        float delta1 = z1n - z1;
        float dm1    = 0.5f * (d1 + d1n) - 1.0f;
        a1 = 1.0f - __expf(-softplus_f(dm1) * delta1);
    }

    float f0 = 1.0f - a0 + 1e-10f;
    float f1 = (lane < 31) ? (1.0f - a1 + 1e-10f) : 1.0f;

    // ---- exclusive cumprod via warp inclusive scans ----
    float P0 = f0, P1 = f1;
    #pragma unroll
    for (int dstep = 1; dstep < 32; dstep <<= 1) {
        float t0 = __shfl_up_sync(FULL, P0, dstep);
        float t1 = __shfl_up_sync(FULL, P1, dstep);
        if (lane >= dstep) { P0 *= t0; P1 *= t1; }
    }
    float e0   = __shfl_up_sync(FULL, P0, 1);
    float e1   = __shfl_up_sync(FULL, P1, 1);
    float tot0 = __shfl_sync(FULL, P0, 31);
    float T0 = (lane == 0) ? 1.0f : e0;
    float T1 = tot0 * ((lane == 0) ? 1.0f : e1);

    float w0 = a0 * T0;          // weight for interval s = lane
    float w1 = a1 * T1;          // weight for interval s = 32+lane (lane31 -> 0)

    // ---- write weights output (coalesced) ----
    float* ow = out + OFF_W + (long long)ray * 63;
    ow[lane] = w0;
    if (lane < 31) ow[32 + lane] = w1;

    // ---- v_t = 0.5*(w_t + w_{t-1}) : converts midpoint sums to plain dots ----
    float wp0 = __shfl_up_sync(FULL, w0, 1);
    float wp1 = __shfl_up_sync(FULL, w1, 1);
    float wlast0 = __shfl_sync(FULL, w0, 31);
    float v0 = 0.5f * (w0 + ((lane == 0) ? 0.0f : wp0));
    float v1 = 0.5f * (w1 + ((lane == 0) ? wlast0 : wp1));

    s_v[w][lane]      = v0;
    s_v[w][32 + lane] = v1;

    // ---- grads (lane t strided by 3 floats: conflict/coalesce friendly) ----
    const float* gb = grads + (long long)ray * 192;
    float g00 = gb[lane * 3 + 0], g01 = gb[lane * 3 + 1], g02 = gb[lane * 3 + 2];
    float g10 = gb[96 + lane * 3 + 0], g11 = gb[96 + lane * 3 + 1], g12 = gb[96 + lane * 3 + 2];

    // ---- scalar partials ----
    float wt  = w0 + w1;
    float dsm = v0 * z0  + v1 * z1;
    float ag0 = v0 * g00 + v1 * g10;
    float ag1 = v0 * g01 + v1 * g11;
    float ag2 = v0 * g02 + v1 * g12;

    #pragma unroll
    for (int dstep = 16; dstep; dstep >>= 1) {
        wt  += __shfl_xor_sync(FULL, wt,  dstep);
        dsm += __shfl_xor_sync(FULL, dsm, dstep);
        ag0 += __shfl_xor_sync(FULL, ag0, dstep);
        ag1 += __shfl_xor_sync(FULL, ag1, dstep);
        ag2 += __shfl_xor_sync(FULL, ag2, dstep);
    }

    __syncwarp();

    // ---- color dot products: lane = (sample-phase g, channel-quad q) ----
    const int q = lane & 7;      // channels 4q..4q+3
    const int g = lane >> 3;     // samples t = g, g+4, g+8, ...
    const float4* cp = reinterpret_cast<const float4*>(colors + (long long)ray * 2048) + q;

    float4 acc = make_float4(0.f, 0.f, 0.f, 0.f);
    #pragma unroll
    for (int i = 0; i < 16; i++) {
        int t = g + 4 * i;
        float4 cv = cp[t * 8];           // row stride = 32 floats = 8 float4
        float  vt = s_v[w][t];
        acc.x = fmaf(vt, cv.x, acc.x);
        acc.y = fmaf(vt, cv.y, acc.y);
        acc.z = fmaf(vt, cv.z, acc.z);
        acc.w = fmaf(vt, cv.w, acc.w);
    }
    // reduce across the 4 sample-phase groups (lanes q, q+8, q+16, q+24)
    #pragma unroll
    for (int dstep = 8; dstep < 32; dstep <<= 1) {
        acc.x += __shfl_xor_sync(FULL, acc.x, dstep);
        acc.y += __shfl_xor_sync(FULL, acc.y, dstep);
        acc.z += __shfl_xor_sync(FULL, acc.z, dstep);
        acc.w += __shfl_xor_sync(FULL, acc.w, dstep);
    }

    if (lane < 8) {
        float4 r = make_float4(acc.x * 2.0f - 1.0f, acc.y * 2.0f - 1.0f,
                               acc.z * 2.0f - 1.0f, acc.w * 2.0f - 1.0f);
        reinterpret_cast<float4*>(out)[(long long)ray * 8 + q] = r;
    }

    if (lane == 0) {
        float dmin = unflipf(g_min_bits);
        float dmax = unflipf(g_max_bits);
        float dd = dsm / wt;
        if (isnan(dd)) dd = __int_as_float(0x7F800000);  // +inf
        dd = fminf(fmaxf(dd, dmin), dmax);
        out[OFF_DEPTH + ray] = dd;
    }

    if (lane < 3) {
        float val = (lane == 0) ? ag0 : (lane == 1) ? ag1 : ag2;
        out[OFF_G + (long long)ray * 3 + lane] = val + 1.0f - wt;
    }
}

extern "C" void kernel_launch(void* const* d_in, const int* in_sizes, int n_in,
                              void* d_out, int out_size) {
    const float* colors = (const float*)d_in[0];
    const float* dens   = (const float*)d_in[1];
    const float* dep    = (const float*)d_in[2];
    const float* grads  = (const float*)d_in[3];
    float* out = (float*)d_out;

    mm_init_kernel<<<1, 1>>>();
    mm_reduce_kernel<<<1024, 256>>>((const float4*)dep, N_DEPTH_ELEMS / 4);
    march_kernel<<<RAYS / 8, 256>>>(colors, dens, dep, grads, out);
}